// round 8
// baseline (speedup 1.0000x reference)
#include <cuda_runtime.h>
#include <cuda_bf16.h>

#define N_SPARSE 20
#define N_VARLEN 3
#define SEQ_LEN  50
#define VOCAB    100000
#define N_DENSE  13
#define VAR_TOT  (N_VARLEN * SEQ_LEN)   // 150

// Vocab slice [0, S_SLICE) of the 3 varlen tables cached in smem.
// 3 * 19328 * 4 = 231936 B <= 232448 B (sm_103a max dynamic smem).
#define S_SLICE     19328
#define SLICE_BYTES (3 * S_SLICE * 4)

#define GRID_CTAS   152   // GB300: 152 SMs, 1 CTA/SM (smem-limited), persistent

__global__ __launch_bounds__(1024, 1) void linear_logit_kernel(
    const int*   __restrict__ sparse_ids,     // [B, 20]
    const int*   __restrict__ varlen_ids,     // [B, 3, 50]
    const float* __restrict__ dense_x,        // [B, 13]
    const float* __restrict__ sparse_tables,  // [20, 100000]
    const float* __restrict__ varlen_tables,  // [3, 100000]
    const float* __restrict__ dense_w,        // [13]
    float*       __restrict__ out,            // [B]
    int B)
{
    extern __shared__ float s_v[];            // [3][S_SLICE], feature-major

    // ---- Load vocab slice of varlen tables into smem (coalesced float4) ----
    #pragma unroll
    for (int f = 0; f < N_VARLEN; f++) {
        const float4* src = (const float4*)(varlen_tables + (long)f * VOCAB);
        float4*       dst = (float4*)(s_v + f * S_SLICE);
        for (int i = threadIdx.x; i < S_SLICE / 4; i += blockDim.x)
            dst[i] = src[i];
    }
    __syncthreads();

    const int warp = threadIdx.x >> 5;        // 0..31
    const int lane = threadIdx.x & 31;
    const int row_stride = gridDim.x * 32;    // 152 * 32 warps

    for (int row = blockIdx.x * 32 + warp; row < B; row += row_stride) {
        float acc = 0.0f;

        // ---- Phase 1: batch all index loads (front-loaded LDGs, high MLP) ----
        int sid = -1;
        if (lane < N_SPARSE)
            sid = __ldg(sparse_ids + (long)row * N_SPARSE + lane);

        const int* vrow = varlen_ids + (long)row * VAR_TOT;
        int vid[5];
        #pragma unroll
        for (int i = 0; i < 5; i++) {
            int idx = lane + i * 32;
            vid[i] = (idx < VAR_TOT) ? __ldg(vrow + idx) : 0;
        }

        float dx = 0.0f, dw = 0.0f;
        if (lane < N_DENSE) {
            dx = __ldg(dense_x + (long)row * N_DENSE + lane);
            dw = __ldg(dense_w + lane);
        }

        // ---- Phase 2a: sparse gathers (L2-resident, divergent LDG) ----
        if (sid >= 0)
            acc += __ldg(sparse_tables + lane * VOCAB + sid);

        // ---- Phase 2b: varlen gathers — smem slice hit or LDG fallback ----
        #pragma unroll
        for (int i = 0; i < 5; i++) {
            int idx = lane + i * 32;
            if (idx < VAR_TOT && vid[i] != 0) {
                int f = idx / SEQ_LEN;              // 0..2
                if (vid[i] < S_SLICE) {
                    acc += s_v[f * S_SLICE + vid[i]];
                } else {
                    acc += __ldg(varlen_tables + f * VOCAB + vid[i]);
                }
            }
        }

        acc += dx * dw;

        // ---- Phase 3: warp reduction ----
        #pragma unroll
        for (int off = 16; off; off >>= 1)
            acc += __shfl_down_sync(0xffffffffu, acc, off);

        if (lane == 0)
            out[row] = acc;
    }
}

extern "C" void kernel_launch(void* const* d_in, const int* in_sizes, int n_in,
                              void* d_out, int out_size)
{
    const int*   sparse_ids    = (const int*)  d_in[0];
    const int*   varlen_ids    = (const int*)  d_in[1];
    const float* dense_x       = (const float*)d_in[2];
    const float* sparse_tables = (const float*)d_in[3];
    const float* varlen_tables = (const float*)d_in[4];
    const float* dense_w       = (const float*)d_in[5];
    float*       out           = (float*)d_out;

    const int B = in_sizes[0] / N_SPARSE;   // 65536

    cudaFuncSetAttribute(linear_logit_kernel,
                         cudaFuncAttributeMaxDynamicSharedMemorySize,
                         SLICE_BYTES);

    linear_logit_kernel<<<GRID_CTAS, 1024, SLICE_BYTES>>>(
        sparse_ids, varlen_ids, dense_x,
        sparse_tables, varlen_tables, dense_w,
        out, B);
}

// round 9
// speedup vs baseline: 1.7419x; 1.7419x over previous
#include <cuda_runtime.h>
#include <cuda_bf16.h>

#define N_SPARSE 20
#define N_VARLEN 3
#define SEQ_LEN  50
#define VOCAB    100000
#define N_DENSE  13
#define VAR_TOT  (N_VARLEN * SEQ_LEN)   // 150

// 8 CTAs/SM * 152 SMs; 8 warps/CTA -> 9728 warps, ~6.7 rows per warp,
// grid-stride with 1-row index prefetch (software pipeline).
#define GRID_CTAS (152 * 8)
#define THREADS   256

struct RowIdx {
    int   sid;      // sparse id for this lane (lane < 20), else -1
    int   vid[5];   // varlen ids, lane + 32*i
    float dx;       // dense_x element (lane < 13), else 0
};

__device__ __forceinline__ void load_row_idx(
    int row, int lane,
    const int*   __restrict__ sparse_ids,
    const int*   __restrict__ varlen_ids,
    const float* __restrict__ dense_x,
    RowIdx& r)
{
    r.sid = (lane < N_SPARSE) ? __ldg(sparse_ids + (long)row * N_SPARSE + lane) : -1;

    const int* vrow = varlen_ids + (long)row * VAR_TOT;
    // i = 0..3: idx = lane + 32*i <= 127 < 150, always in range
    #pragma unroll
    for (int i = 0; i < 4; i++)
        r.vid[i] = __ldg(vrow + lane + i * 32);
    // i = 4: idx in [128, 159], predicate on < 150
    r.vid[4] = (lane + 128 < VAR_TOT) ? __ldg(vrow + lane + 128) : 0;

    r.dx = (lane < N_DENSE) ? __ldg(dense_x + (long)row * N_DENSE + lane) : 0.0f;
}

__global__ __launch_bounds__(THREADS) void linear_logit_kernel(
    const int*   __restrict__ sparse_ids,     // [B, 20]
    const int*   __restrict__ varlen_ids,     // [B, 3, 50]
    const float* __restrict__ dense_x,        // [B, 13]
    const float* __restrict__ sparse_tables,  // [20, 100000]
    const float* __restrict__ varlen_tables,  // [3, 100000]
    const float* __restrict__ dense_w,        // [13]
    float*       __restrict__ out,            // [B]
    int B)
{
    const int lane   = threadIdx.x & 31;
    const int gwarp  = (blockIdx.x * THREADS + threadIdx.x) >> 5;
    const int nwarps = GRID_CTAS * (THREADS / 32);

    // Loop-invariant: dense weight for this lane
    const float dw = (lane < N_DENSE) ? __ldg(dense_w + lane) : 0.0f;

    int row = gwarp;
    if (row >= B) return;

    // Prologue: prefetch first row's indices
    RowIdx cur;
    load_row_idx(row, lane, sparse_ids, varlen_ids, dense_x, cur);

    while (row < B) {
        const int nrow = row + nwarps;

        // ---- Prefetch next row's indices BEFORE current gathers ----
        // (independent loads; by next iteration they've landed -> no exposed
        //  index-load latency inside the steady-state loop)
        RowIdx nxt;
        if (nrow < B)
            load_row_idx(nrow, lane, sparse_ids, varlen_ids, dense_x, nxt);

        // ---- Gathers for current row (L2-resident tables) ----
        float acc = cur.dx * dw;

        if (cur.sid >= 0)
            acc += __ldg(sparse_tables + lane * VOCAB + cur.sid);

        #pragma unroll
        for (int i = 0; i < 5; i++) {
            const int idx = lane + i * 32;
            bool live = (i < 4) || (idx < VAR_TOT);
            if (live && cur.vid[i] != 0) {
                const int f = (idx >= 2 * SEQ_LEN) ? 2 : (idx >= SEQ_LEN ? 1 : 0);
                acc += __ldg(varlen_tables + f * VOCAB + cur.vid[i]);
            }
        }

        // ---- Warp reduction + store ----
        #pragma unroll
        for (int off = 16; off; off >>= 1)
            acc += __shfl_down_sync(0xffffffffu, acc, off);

        if (lane == 0)
            out[row] = acc;

        // ---- Rotate pipeline ----
        row = nrow;
        cur = nxt;
    }
}

extern "C" void kernel_launch(void* const* d_in, const int* in_sizes, int n_in,
                              void* d_out, int out_size)
{
    const int*   sparse_ids    = (const int*)  d_in[0];
    const int*   varlen_ids    = (const int*)  d_in[1];
    const float* dense_x       = (const float*)d_in[2];
    const float* sparse_tables = (const float*)d_in[3];
    const float* varlen_tables = (const float*)d_in[4];
    const float* dense_w       = (const float*)d_in[5];
    float*       out           = (float*)d_out;

    const int B = in_sizes[0] / N_SPARSE;   // 65536

    linear_logit_kernel<<<GRID_CTAS, THREADS>>>(
        sparse_ids, varlen_ids, dense_x,
        sparse_tables, varlen_tables, dense_w,
        out, B);
}

// round 10
// speedup vs baseline: 1.7600x; 1.0104x over previous
#include <cuda_runtime.h>
#include <cuda_bf16.h>

#define N_SPARSE 20
#define N_VARLEN 3
#define SEQ_LEN  50
#define VOCAB    100000
#define N_DENSE  13
#define VAR_TOT  (N_VARLEN * SEQ_LEN)   // 150
#define VAR_2ROW (2 * VAR_TOT)          // 300

#define THREADS  256
// 2 rows per warp, 8 warps per CTA -> 16 rows per CTA
#define ROWS_PER_CTA (2 * (THREADS / 32))

__global__ __launch_bounds__(THREADS) void linear_logit_kernel(
    const int*   __restrict__ sparse_ids,     // [B, 20]
    const int*   __restrict__ varlen_ids,     // [B, 3, 50]
    const float* __restrict__ dense_x,        // [B, 13]
    const float* __restrict__ sparse_tables,  // [20, 100000]
    const float* __restrict__ varlen_tables,  // [3, 100000]
    const float* __restrict__ dense_w,        // [13]
    float*       __restrict__ out,            // [B]
    int B)
{
    const int lane  = threadIdx.x & 31;
    const int gwarp = (blockIdx.x * THREADS + threadIdx.x) >> 5;
    const int r0    = gwarp * 2;              // first of the adjacent row pair
    if (r0 >= B) return;
    const int r1 = r0 + 1;                    // B is even (65536); always valid

    // ---------- Phase 1: batch ALL index loads (max front-loaded MLP) ----------
    // Sparse ids: two adjacent 20-int rows.
    const int sid0 = (lane < N_SPARSE) ? __ldg(sparse_ids + (long)r0 * N_SPARSE + lane) : -1;
    const int sid1 = (lane < N_SPARSE) ? __ldg(sparse_ids + (long)r1 * N_SPARSE + lane) : -1;

    // Varlen ids: the pair is one contiguous 300-int block -> 10 coalesced LDGs.
    const int* vbase = varlen_ids + (long)r0 * VAR_TOT;
    int vid[10];
    #pragma unroll
    for (int i = 0; i < 10; i++) {
        const int c = lane + i * 32;
        vid[i] = (c < VAR_2ROW) ? __ldg(vbase + c) : 0;   // only i=9 tail masked
    }

    // Dense.
    const float dw  = (lane < N_DENSE) ? __ldg(dense_w + lane) : 0.0f;
    const float dx0 = (lane < N_DENSE) ? __ldg(dense_x + (long)r0 * N_DENSE + lane) : 0.0f;
    const float dx1 = (lane < N_DENSE) ? __ldg(dense_x + (long)r1 * N_DENSE + lane) : 0.0f;

    float acc0 = dx0 * dw;
    float acc1 = dx1 * dw;

    // ---------- Phase 2: 42 independent gathers (L2-resident tables) ----------
    if (sid0 >= 0) acc0 += __ldg(sparse_tables + lane * VOCAB + sid0);
    if (sid1 >= 0) acc1 += __ldg(sparse_tables + lane * VOCAB + sid1);

    #pragma unroll
    for (int i = 0; i < 10; i++) {
        const int c = lane + i * 32;          // 0..319 over the 2-row block
        const bool live = (i < 9 || c < VAR_2ROW) && (vid[i] != 0);
        if (live) {
            // feature = (c/50) % 3 ; constant-folds for non-straddling i
            const int f = (c / SEQ_LEN) % N_VARLEN;
            const float v = __ldg(varlen_tables + f * VOCAB + vid[i]);
            // which row: c < 150 -> r0, else r1 (compile-time except i=4)
            if (i < 4)       acc0 += v;
            else if (i > 4)  acc1 += v;
            else { if (c < VAR_TOT) acc0 += v; else acc1 += v; }
        }
    }

    // ---------- Phase 3: two independent warp reductions ----------
    #pragma unroll
    for (int off = 16; off; off >>= 1) {
        acc0 += __shfl_down_sync(0xffffffffu, acc0, off);
        acc1 += __shfl_down_sync(0xffffffffu, acc1, off);
    }

    if (lane == 0) {
        out[r0] = acc0;
        out[r1] = acc1;
    }
}

extern "C" void kernel_launch(void* const* d_in, const int* in_sizes, int n_in,
                              void* d_out, int out_size)
{
    const int*   sparse_ids    = (const int*)  d_in[0];
    const int*   varlen_ids    = (const int*)  d_in[1];
    const float* dense_x       = (const float*)d_in[2];
    const float* sparse_tables = (const float*)d_in[3];
    const float* varlen_tables = (const float*)d_in[4];
    const float* dense_w       = (const float*)d_in[5];
    float*       out           = (float*)d_out;

    const int B = in_sizes[0] / N_SPARSE;     // 65536

    const int blocks = (B + ROWS_PER_CTA - 1) / ROWS_PER_CTA;   // 4096

    linear_logit_kernel<<<blocks, THREADS>>>(
        sparse_ids, varlen_ids, dense_x,
        sparse_tables, varlen_tables, dense_w,
        out, B);
}